// round 8
// baseline (speedup 1.0000x reference)
#include <cuda_runtime.h>

#define B_  2
#define DD  64
#define HH  256
#define WW  256
#define HW  (HH*WW)
#define DHW (DD*HW)
#define PD  (DD+2)
#define PH  (HH+2)
#define PW  (WW+2)
#define PHW (PH*PW)      // 66564

typedef unsigned long long u64;

// packed f32x2 helpers (two independent IEEE fp32 lanes -> bit-exact)
#define PACK2(out, lo, hi) \
    asm("mov.b64 %0, {%1, %2};" : "=l"(out) : "f"(lo), "f"(hi))
#define FMA2(d, a, b, c) \
    asm("fma.rn.f32x2 %0, %1, %2, %3;" : "=l"(d) : "l"(a), "l"(b), "l"(c))
#define UNPACK2(lo, hi, in) \
    asm("mov.b64 {%0, %1}, %2;" : "=f"(lo), "=f"(hi) : "l"(in))

// Zero-padded moving channel (channel 0), per batch. 35.1 MB.
__device__ float g_xpad[B_ * PD * PHW];
// Packed weights: [kz][ky][kx][c] -> (w_oc0, w_oc1, w_oc2, pad)
__device__ float4 g_wpack[54];
__device__ float  g_bias[3];

// ---------------------------------------------------------------------------
// Kernel 0: pack weights for LDS.128 broadcast. One warp pass.
// ---------------------------------------------------------------------------
__global__ void pack_kernel(const float* __restrict__ wp,
                            const float* __restrict__ bp) {
    int i = threadIdx.x;              // i = (kz*9+ky*3+kx)*2 + c
    if (i < 54) {
        int c  = i & 1;
        int k  = i >> 1;
        int wo = c * 27 + k;
        g_wpack[i] = make_float4(wp[wo], wp[54 + wo], wp[108 + wo], 0.f);
    }
    if (i < 3) g_bias[i] = bp[i];
}

// ---------------------------------------------------------------------------
// Kernel 1: padded moving image. Grid (PH, PD, B_), coalesced, no division.
// ---------------------------------------------------------------------------
__global__ void __launch_bounds__(256) pad_kernel(const float* __restrict__ x) {
    const int y = blockIdx.x;
    const int z = blockIdx.y;
    const int b = blockIdx.z;
    const bool zyok = ((unsigned)(z - 1) < (unsigned)DD) &&
                      ((unsigned)(y - 1) < (unsigned)HH);
    const float* src = x + (size_t)b * 2 * DHW + (size_t)(z - 1) * HW + (y - 1) * WW;
    float* dst = g_xpad + (size_t)b * PD * PHW + (size_t)z * PHW + y * PW;
    #pragma unroll
    for (int s = 0; s < 2; s++) {
        int col = threadIdx.x + s * 256;
        if (col < PW) {
            float v = 0.f;
            int gx = col - 1;
            if (zyok && (unsigned)gx < (unsigned)WW) v = __ldg(src + gx);
            dst[col] = v;
        }
    }
}

// ---------------------------------------------------------------------------
// Kernel 2: fused offset-conv + trilinear deformable sampling.
// lane = x (coalesced), 4 consecutive y per thread (R5 shape). Weights via
// one LDS.128 per (kz,ky,kx,c). Conv accumulation uses fma.rn.f32x2 with the
// 4 independent y-chains packed pairwise -- each lane performs the same IEEE
// FMA sequence (kz->ky->kx->c, exact-zero OOB taps) as the passing R3/R5
// kernels, so the result is bit-identical.
// ---------------------------------------------------------------------------
__global__ void __launch_bounds__(256) reg3d_kernel(
    const float* __restrict__ x,
    float* __restrict__ out)        // [2, 2, 64, 256, 256]
{
    __shared__ float4 swp[54];
    __shared__ float  sb[3];

    const int t = threadIdx.x;             // xi = t (0..255)
    const int blk = blockIdx.x;            // 8192 = 64(yq) * 64(z) * 2(b)
    const int yq = blk & 63;
    const int z  = (blk >> 6) & 63;
    const int b  = blk >> 12;
    const int y0 = yq << 2;

    if (t < 54) swp[t] = g_wpack[t];
    if (t < 3)  sb[t]  = g_bias[t];
    __syncthreads();

    const int xi = t;
    const float* xb = x + (size_t)b * 2 * DHW;

    bool pz[3], py[6];
    #pragma unroll
    for (int kz = 0; kz < 3; kz++) pz[kz] = (unsigned)(z + kz - 1) < (unsigned)DD;
    #pragma unroll
    for (int dy = 0; dy < 6; dy++) py[dy] = (unsigned)(y0 + dy - 1) < (unsigned)HH;
    const bool pxm = (xi >= 1), pxp = (xi < 255);

    const float* base = xb + (ptrdiff_t)(z - 1) * HW + (ptrdiff_t)(y0 - 1) * WW + xi;

    // packed accumulators: A*[0] = {j0,j1}, A*[1] = {j2,j3}
    u64 A0[2], A1[2], A2[2];
    {
        u64 zz64; PACK2(zz64, 0.f, 0.f);
        A0[0] = A0[1] = zz64; A1[0] = A1[1] = zz64; A2[0] = A2[1] = zz64;
    }

    #pragma unroll
    for (int kz = 0; kz < 3; kz++) {
        float vals[2][6][3];   // [c][dy][dx], dx 0/1/2 = x-1/x/x+1
        #pragma unroll
        for (int c = 0; c < 2; c++)
            #pragma unroll
            for (int dy = 0; dy < 6; dy++) {
                const bool rowok = pz[kz] && py[dy];
                const float* p = base + (ptrdiff_t)c * DHW + (ptrdiff_t)kz * HW
                                      + (ptrdiff_t)dy * WW;
                vals[c][dy][0] = (rowok && pxm) ? __ldg(p - 1) : 0.f;
                vals[c][dy][1] = rowok          ? __ldg(p)     : 0.f;
                vals[c][dy][2] = (rowok && pxp) ? __ldg(p + 1) : 0.f;
            }

        #pragma unroll
        for (int ky = 0; ky < 3; ky++)
            #pragma unroll
            for (int kx = 0; kx < 3; kx++)
                #pragma unroll
                for (int c = 0; c < 2; c++) {
                    const float4 w = swp[(kz * 9 + ky * 3 + kx) * 2 + c];
                    u64 w0p, w1p, w2p, vp0, vp1;
                    PACK2(w0p, w.x, w.x);
                    PACK2(w1p, w.y, w.y);
                    PACK2(w2p, w.z, w.z);
                    PACK2(vp0, vals[c][ky][kx],     vals[c][ky + 1][kx]);
                    PACK2(vp1, vals[c][ky + 2][kx], vals[c][ky + 3][kx]);
                    FMA2(A0[0], vp0, w0p, A0[0]);
                    FMA2(A0[1], vp1, w0p, A0[1]);
                    FMA2(A1[0], vp0, w1p, A1[0]);
                    FMA2(A1[1], vp1, w1p, A1[1]);
                    FMA2(A2[0], vp0, w2p, A2[0]);
                    FMA2(A2[1], vp1, w2p, A2[1]);
                }
    }

    float a0[4], a1[4], a2[4];
    UNPACK2(a0[0], a0[1], A0[0]); UNPACK2(a0[2], a0[3], A0[1]);
    UNPACK2(a1[0], a1[1], A1[0]); UNPACK2(a1[2], a1[3], A1[1]);
    UNPACK2(a2[0], a2[1], A2[0]); UNPACK2(a2[2], a2[3], A2[1]);

    // ---- sampling (op-for-op faithful) ----
    const float* xpad = g_xpad + (size_t)b * PD * PHW;
    const size_t rowbase = (size_t)b * 2 * DHW + (size_t)z * HW;
    const float b0 = sb[0], b1 = sb[1], b2 = sb[2];

    #pragma unroll
    for (int j = 0; j < 4; j++) {
        const int y = y0 + j;
        float oz = __fadd_rn(a0[j], b0);
        float oy = __fadd_rn(a1[j], b1);
        float ox = __fadd_rn(a2[j], b2);

        float qz = fminf(fmaxf(__fadd_rn((float)(z + 1), oz), 0.f), 64.f);
        float qy = fminf(fmaxf(__fadd_rn((float)(y + 1), oy), 0.f), 256.f);
        float qx = fminf(fmaxf(__fadd_rn((float)(xi + 1), ox), 0.f), 256.f);

        float lz = __fadd_rn(qz, -floorf(qz));
        float ly = __fadd_rn(qy, -floorf(qy));
        float lx = __fadd_rn(qx, -floorf(qx));
        float wz0 = __fadd_rn(1.f, -lz);
        float wy0 = __fadd_rn(1.f, -ly);
        float wx0 = __fadd_rn(1.f, -lx);

        float acc = 0.f;
        #pragma unroll
        for (int dz = 0; dz < 2; dz++) {
            float cz = __fadd_rn(qz, (float)dz);
            float wz = dz ? lz : wz0;
            float czp = __fmul_rn(cz, (float)PHW);
            #pragma unroll
            for (int dy = 0; dy < 2; dy++) {
                float cy  = __fadd_rn(qy, (float)dy);
                float wzy = __fmul_rn(wz, dy ? ly : wy0);
                float czyp = __fadd_rn(czp, __fmul_rn(cy, (float)PW));
                #pragma unroll
                for (int dx = 0; dx < 2; dx++) {
                    float cx   = __fadd_rn(qx, (float)dx);
                    float comb = __fadd_rn(czyp, cx);
                    unsigned idx = (unsigned)comb;   // trunc (astype int32)
                    float wv = __fmul_rn(wzy, dx ? lx : wx0);
                    acc = __fadd_rn(acc, __fmul_rn(__ldg(xpad + idx), wv));
                }
            }
        }

        out[rowbase + (size_t)y * WW + xi] = acc;   // deformed channel
    }
}

// ---------------------------------------------------------------------------
extern "C" void kernel_launch(void* const* d_in, const int* in_sizes, int n_in,
                              void* d_out, int out_size) {
    const float* x  = (const float*)d_in[0];
    const float* wp = (const float*)d_in[1];
    const float* bp = (const float*)d_in[2];
    float* out = (float*)d_out;

    pack_kernel<<<1, 64>>>(wp, bp);

    // fixed channel: out[:,1] = x[:,1] (D2D copy, overlaps with kernels)
    cudaMemcpyAsync(out + DHW,             x + DHW,             (size_t)DHW * 4,
                    cudaMemcpyDeviceToDevice);
    cudaMemcpyAsync(out + 3 * (size_t)DHW, x + 3 * (size_t)DHW, (size_t)DHW * 4,
                    cudaMemcpyDeviceToDevice);

    dim3 pgrid(PH, PD, B_);
    pad_kernel<<<pgrid, 256>>>(x);

    // 2(b) * 64(z) * 64(y-quads) = 8192 blocks, 256 threads = full x row
    reg3d_kernel<<<8192, 256>>>(x, out);
}

// round 9
// speedup vs baseline: 1.1012x; 1.1012x over previous
#include <cuda_runtime.h>

#define B_  2
#define DD  64
#define HH  256
#define WW  256
#define HW  (HH*WW)
#define DHW (DD*HW)
#define PD  (DD+2)
#define PH  (HH+2)
#define PW  (WW+2)
#define PHW (PH*PW)      // 66564

// Zero-padded moving channel (channel 0), per batch. 35.1 MB.
__device__ float g_xpad[B_ * PD * PHW];
// Packed weights: [kz][ky][kx][c] -> (w_oc0, w_oc1, w_oc2, pad)
__device__ float4 g_wpack[54];
__device__ float  g_bias[3];

// ---------------------------------------------------------------------------
// Kernel 1: padded moving image. Grid (PH, PD, B_), coalesced, no division.
// Block (0,0,0) additionally packs the conv weights (runs before reg3d).
// ---------------------------------------------------------------------------
__global__ void __launch_bounds__(256) pad_kernel(const float* __restrict__ x,
                                                  const float* __restrict__ wp,
                                                  const float* __restrict__ bp) {
    const int y = blockIdx.x;
    const int z = blockIdx.y;
    const int b = blockIdx.z;

    if (y == 0 && z == 0 && b == 0) {
        int i = threadIdx.x;          // i = (kz*9+ky*3+kx)*2 + c
        if (i < 54) {
            int c  = i & 1;
            int k  = i >> 1;
            int wo = c * 27 + k;
            g_wpack[i] = make_float4(wp[wo], wp[54 + wo], wp[108 + wo], 0.f);
        }
        if (i < 3) g_bias[i] = bp[i];
    }

    const bool zyok = ((unsigned)(z - 1) < (unsigned)DD) &&
                      ((unsigned)(y - 1) < (unsigned)HH);
    const float* src = x + (size_t)b * 2 * DHW + (size_t)(z - 1) * HW + (y - 1) * WW;
    float* dst = g_xpad + (size_t)b * PD * PHW + (size_t)z * PHW + y * PW;
    #pragma unroll
    for (int s = 0; s < 2; s++) {
        int col = threadIdx.x + s * 256;
        if (col < PW) {
            float v = 0.f;
            int gx = col - 1;
            if (zyok && (unsigned)gx < (unsigned)WW) v = __ldg(src + gx);
            dst[col] = v;
        }
    }
}

// ---------------------------------------------------------------------------
// Kernel 2: fused offset-conv + trilinear deformable sampling + fixed copy.
// Identical structure to the 200us R5 kernel (lane = x, 4 consecutive y per
// thread, direct 3-LDG x-halo, scalar FMA order kz->ky->kx->c with exact-zero
// OOB taps -> bit-identical results). Single change vs R5: weights fetched as
// one LDS.128 broadcast per (kz,ky,kx,c) (54 wavefronts) instead of 162
// scalar LDS.
// ---------------------------------------------------------------------------
__global__ void __launch_bounds__(256) reg3d_kernel(
    const float* __restrict__ x,
    float* __restrict__ out)        // [2, 2, 64, 256, 256]
{
    __shared__ float4 swp[54];
    __shared__ float  sb[3];

    const int t = threadIdx.x;             // xi = t (0..255)
    const int blk = blockIdx.x;            // 8192 = 64(yq) * 64(z) * 2(b)
    const int yq = blk & 63;
    const int z  = (blk >> 6) & 63;
    const int b  = blk >> 12;
    const int y0 = yq << 2;

    if (t < 54) swp[t] = g_wpack[t];
    if (t < 3)  sb[t]  = g_bias[t];
    __syncthreads();

    const int xi = t;
    const float* xb = x + (size_t)b * 2 * DHW;

    bool pz[3], py[6];
    #pragma unroll
    for (int kz = 0; kz < 3; kz++) pz[kz] = (unsigned)(z + kz - 1) < (unsigned)DD;
    #pragma unroll
    for (int dy = 0; dy < 6; dy++) py[dy] = (unsigned)(y0 + dy - 1) < (unsigned)HH;
    const bool pxm = (xi >= 1), pxp = (xi < 255);

    const float* base = xb + (ptrdiff_t)(z - 1) * HW + (ptrdiff_t)(y0 - 1) * WW + xi;

    // ---- conv: 3 out channels x 4 y, FMA kz->ky->kx->c ----
    float a0[4], a1[4], a2[4];
    #pragma unroll
    for (int j = 0; j < 4; j++) { a0[j] = 0.f; a1[j] = 0.f; a2[j] = 0.f; }

    #pragma unroll
    for (int kz = 0; kz < 3; kz++) {
        float vals[2][6][3];   // [c][dy][dx], dx 0/1/2 = x-1/x/x+1
        #pragma unroll
        for (int c = 0; c < 2; c++)
            #pragma unroll
            for (int dy = 0; dy < 6; dy++) {
                const bool rowok = pz[kz] && py[dy];
                const float* p = base + (ptrdiff_t)c * DHW + (ptrdiff_t)kz * HW
                                      + (ptrdiff_t)dy * WW;
                vals[c][dy][0] = (rowok && pxm) ? __ldg(p - 1) : 0.f;
                vals[c][dy][1] = rowok          ? __ldg(p)     : 0.f;
                vals[c][dy][2] = (rowok && pxp) ? __ldg(p + 1) : 0.f;
            }

        #pragma unroll
        for (int ky = 0; ky < 3; ky++)
            #pragma unroll
            for (int kx = 0; kx < 3; kx++)
                #pragma unroll
                for (int c = 0; c < 2; c++) {
                    const float4 w = swp[(kz * 9 + ky * 3 + kx) * 2 + c];
                    #pragma unroll
                    for (int j = 0; j < 4; j++) {
                        const float v = vals[c][j + ky][kx];
                        a0[j] = __fmaf_rn(v, w.x, a0[j]);
                        a1[j] = __fmaf_rn(v, w.y, a1[j]);
                        a2[j] = __fmaf_rn(v, w.z, a2[j]);
                    }
                }
    }

    // ---- sampling (op-for-op faithful) ----
    const float* xpad = g_xpad + (size_t)b * PD * PHW;
    const size_t rowbase = (size_t)b * 2 * DHW + (size_t)z * HW;
    const float b0 = sb[0], b1 = sb[1], b2 = sb[2];

    #pragma unroll
    for (int j = 0; j < 4; j++) {
        const int y = y0 + j;
        float oz = __fadd_rn(a0[j], b0);
        float oy = __fadd_rn(a1[j], b1);
        float ox = __fadd_rn(a2[j], b2);

        float qz = fminf(fmaxf(__fadd_rn((float)(z + 1), oz), 0.f), 64.f);
        float qy = fminf(fmaxf(__fadd_rn((float)(y + 1), oy), 0.f), 256.f);
        float qx = fminf(fmaxf(__fadd_rn((float)(xi + 1), ox), 0.f), 256.f);

        float lz = __fadd_rn(qz, -floorf(qz));
        float ly = __fadd_rn(qy, -floorf(qy));
        float lx = __fadd_rn(qx, -floorf(qx));
        float wz0 = __fadd_rn(1.f, -lz);
        float wy0 = __fadd_rn(1.f, -ly);
        float wx0 = __fadd_rn(1.f, -lx);

        float acc = 0.f;
        #pragma unroll
        for (int dz = 0; dz < 2; dz++) {
            float cz = __fadd_rn(qz, (float)dz);
            float wz = dz ? lz : wz0;
            float czp = __fmul_rn(cz, (float)PHW);
            #pragma unroll
            for (int dy = 0; dy < 2; dy++) {
                float cy  = __fadd_rn(qy, (float)dy);
                float wzy = __fmul_rn(wz, dy ? ly : wy0);
                float czyp = __fadd_rn(czp, __fmul_rn(cy, (float)PW));
                #pragma unroll
                for (int dx = 0; dx < 2; dx++) {
                    float cx   = __fadd_rn(qx, (float)dx);
                    float comb = __fadd_rn(czyp, cx);
                    unsigned idx = (unsigned)comb;   // trunc (astype int32)
                    float wv = __fmul_rn(wzy, dx ? lx : wx0);
                    acc = __fadd_rn(acc, __fmul_rn(__ldg(xpad + idx), wv));
                }
            }
        }

        const size_t o0 = rowbase + (size_t)y * WW + xi;
        out[o0] = acc;                                            // deformed
        out[o0 + DHW] = __ldg(xb + DHW + (size_t)z * HW + (size_t)y * WW + xi); // fixed
    }
}

// ---------------------------------------------------------------------------
extern "C" void kernel_launch(void* const* d_in, const int* in_sizes, int n_in,
                              void* d_out, int out_size) {
    const float* x  = (const float*)d_in[0];
    const float* wp = (const float*)d_in[1];
    const float* bp = (const float*)d_in[2];
    float* out = (float*)d_out;

    dim3 pgrid(PH, PD, B_);
    pad_kernel<<<pgrid, 256>>>(x, wp, bp);

    // 2(b) * 64(z) * 64(y-quads) = 8192 blocks, 256 threads = full x row
    reg3d_kernel<<<8192, 256>>>(x, out);
}

// round 10
// speedup vs baseline: 1.1559x; 1.0497x over previous
#include <cuda_runtime.h>

#define B_  2
#define DD  64
#define HH  256
#define WW  256
#define HW  (HH*WW)
#define DHW (DD*HW)
#define PD  (DD+2)
#define PH  (HH+2)
#define PW  (WW+2)
#define PHW (PH*PW)      // 66564

// Zero-padded moving channel (channel 0), per batch. 35.1 MB.
__device__ float g_xpad[B_ * PD * PHW];

// ---------------------------------------------------------------------------
// Kernel 1: padded moving image. Grid (PH, PD, B_), 288 threads cover the
// 258-wide row in one step. Coalesced, no division.
// ---------------------------------------------------------------------------
__global__ void __launch_bounds__(288) pad_kernel(const float* __restrict__ x) {
    const int y = blockIdx.x;
    const int z = blockIdx.y;
    const int b = blockIdx.z;
    const int col = threadIdx.x;
    if (col >= PW) return;
    const bool zyok = ((unsigned)(z - 1) < (unsigned)DD) &&
                      ((unsigned)(y - 1) < (unsigned)HH);
    float v = 0.f;
    const int gx = col - 1;
    if (zyok && (unsigned)gx < (unsigned)WW) {
        v = __ldg(x + (size_t)b * 2 * DHW + (size_t)(z - 1) * HW + (y - 1) * WW + gx);
    }
    g_xpad[(size_t)b * PD * PHW + (size_t)z * PHW + y * PW + col] = v;
}

// ---------------------------------------------------------------------------
// Faithful trilinear sampler + output store (shared by both conv paths).
// ---------------------------------------------------------------------------
__device__ __forceinline__ void sample_store(
    const float a0[4], const float a1[4], const float a2[4],
    const float* __restrict__ xb, const float* __restrict__ xpad,
    float* __restrict__ out, float b0, float b1, float b2,
    int b, int z, int y0, int xi)
{
    const size_t rowbase = (size_t)b * 2 * DHW + (size_t)z * HW;

    #pragma unroll
    for (int j = 0; j < 4; j++) {
        const int y = y0 + j;
        float oz = __fadd_rn(a0[j], b0);
        float oy = __fadd_rn(a1[j], b1);
        float ox = __fadd_rn(a2[j], b2);

        float qz = fminf(fmaxf(__fadd_rn((float)(z + 1), oz), 0.f), 64.f);
        float qy = fminf(fmaxf(__fadd_rn((float)(y + 1), oy), 0.f), 256.f);
        float qx = fminf(fmaxf(__fadd_rn((float)(xi + 1), ox), 0.f), 256.f);

        float lz = __fadd_rn(qz, -floorf(qz));
        float ly = __fadd_rn(qy, -floorf(qy));
        float lx = __fadd_rn(qx, -floorf(qx));
        float wz0 = __fadd_rn(1.f, -lz);
        float wy0 = __fadd_rn(1.f, -ly);
        float wx0 = __fadd_rn(1.f, -lx);

        float acc = 0.f;
        #pragma unroll
        for (int dz = 0; dz < 2; dz++) {
            float cz = __fadd_rn(qz, (float)dz);
            float wz = dz ? lz : wz0;
            float czp = __fmul_rn(cz, (float)PHW);
            #pragma unroll
            for (int dy = 0; dy < 2; dy++) {
                float cy  = __fadd_rn(qy, (float)dy);
                float wzy = __fmul_rn(wz, dy ? ly : wy0);
                float czyp = __fadd_rn(czp, __fmul_rn(cy, (float)PW));
                #pragma unroll
                for (int dx = 0; dx < 2; dx++) {
                    float cx   = __fadd_rn(qx, (float)dx);
                    float comb = __fadd_rn(czyp, cx);
                    unsigned idx = (unsigned)comb;   // trunc (astype int32)
                    float wv = __fmul_rn(wzy, dx ? lx : wx0);
                    acc = __fadd_rn(acc, __fmul_rn(__ldg(xpad + idx), wv));
                }
            }
        }

        const size_t o0 = rowbase + (size_t)y * WW + xi;
        __stcs(out + o0, acc);                                           // deformed
        __stcs(out + o0 + DHW,
               __ldg(xb + DHW + (size_t)z * HW + (size_t)y * WW + xi));  // fixed
    }
}

// ---------------------------------------------------------------------------
// Conv + sample, templated on INTERIOR (all z/y taps in bounds -> loads
// unconditional; identical values, so bit-exact vs the predicated path).
// FMA order kz->ky->kx->c (c innermost), exact-zero OOB taps: bit-identical
// to the passing R3/R5 kernels.
// ---------------------------------------------------------------------------
template <bool INTERIOR>
__device__ __forceinline__ void conv_sample(
    const float* __restrict__ xb, const float* __restrict__ xpad,
    const float* __restrict__ swt, const float* __restrict__ sb,
    float* __restrict__ out, int b, int z, int y0, int xi)
{
    bool pz[3], py[6];
    if (!INTERIOR) {
        #pragma unroll
        for (int kz = 0; kz < 3; kz++) pz[kz] = (unsigned)(z + kz - 1) < (unsigned)DD;
        #pragma unroll
        for (int dy = 0; dy < 6; dy++) py[dy] = (unsigned)(y0 + dy - 1) < (unsigned)HH;
    }
    const bool pxm = (xi >= 1), pxp = (xi < 255);

    const float* base = xb + (ptrdiff_t)(z - 1) * HW + (ptrdiff_t)(y0 - 1) * WW + xi;

    float a0[4], a1[4], a2[4];
    #pragma unroll
    for (int j = 0; j < 4; j++) { a0[j] = 0.f; a1[j] = 0.f; a2[j] = 0.f; }

    #pragma unroll
    for (int kz = 0; kz < 3; kz++) {
        float vals[2][6][3];   // [c][dy][dx], dx 0/1/2 = x-1/x/x+1
        #pragma unroll
        for (int c = 0; c < 2; c++)
            #pragma unroll
            for (int dy = 0; dy < 6; dy++) {
                const float* p = base + (ptrdiff_t)c * DHW + (ptrdiff_t)kz * HW
                                      + (ptrdiff_t)dy * WW;
                if (INTERIOR) {
                    vals[c][dy][0] = pxm ? __ldg(p - 1) : 0.f;
                    vals[c][dy][1] = __ldg(p);
                    vals[c][dy][2] = pxp ? __ldg(p + 1) : 0.f;
                } else {
                    const bool rowok = pz[kz] && py[dy];
                    vals[c][dy][0] = (rowok && pxm) ? __ldg(p - 1) : 0.f;
                    vals[c][dy][1] = rowok          ? __ldg(p)     : 0.f;
                    vals[c][dy][2] = (rowok && pxp) ? __ldg(p + 1) : 0.f;
                }
            }

        #pragma unroll
        for (int ky = 0; ky < 3; ky++)
            #pragma unroll
            for (int kx = 0; kx < 3; kx++)
                #pragma unroll
                for (int c = 0; c < 2; c++) {
                    const int wo = c * 27 + kz * 9 + ky * 3 + kx;
                    const float w0 = swt[wo];
                    const float w1 = swt[54 + wo];
                    const float w2 = swt[108 + wo];
                    #pragma unroll
                    for (int j = 0; j < 4; j++) {
                        const float v = vals[c][j + ky][kx];
                        a0[j] = __fmaf_rn(v, w0, a0[j]);
                        a1[j] = __fmaf_rn(v, w1, a1[j]);
                        a2[j] = __fmaf_rn(v, w2, a2[j]);
                    }
                }
    }

    sample_store(a0, a1, a2, xb, xpad, out, sb[0], sb[1], sb[2], b, z, y0, xi);
}

__global__ void __launch_bounds__(256) reg3d_kernel(
    const float* __restrict__ x,
    const float* __restrict__ wp,   // [3, 2, 3, 3, 3]
    const float* __restrict__ bp,   // [3]
    float* __restrict__ out)        // [2, 2, 64, 256, 256]
{
    __shared__ float swt[162];
    __shared__ float sb[3];

    const int t = threadIdx.x;             // xi = t (0..255)
    const int blk = blockIdx.x;            // 8192 = 64(yq) * 64(z) * 2(b)
    const int yq = blk & 63;
    const int z  = (blk >> 6) & 63;
    const int b  = blk >> 12;
    const int y0 = yq << 2;

    if (t < 162) swt[t] = wp[t];
    if (t < 3)   sb[t]  = bp[t];
    __syncthreads();

    const float* xb = x + (size_t)b * 2 * DHW;
    const float* xpad = g_xpad + (size_t)b * PD * PHW;

    const bool interior = (z >= 1) && (z <= 62) && (yq >= 1) && (yq <= 62);
    if (interior)
        conv_sample<true >(xb, xpad, swt, sb, out, b, z, y0, t);
    else
        conv_sample<false>(xb, xpad, swt, sb, out, b, z, y0, t);
}

// ---------------------------------------------------------------------------
extern "C" void kernel_launch(void* const* d_in, const int* in_sizes, int n_in,
                              void* d_out, int out_size) {
    const float* x  = (const float*)d_in[0];
    const float* wp = (const float*)d_in[1];
    const float* bp = (const float*)d_in[2];
    float* out = (float*)d_out;

    dim3 pgrid(PH, PD, B_);
    pad_kernel<<<pgrid, 288>>>(x);

    // 2(b) * 64(z) * 64(y-quads) = 8192 blocks, 256 threads = full x row
    reg3d_kernel<<<8192, 256>>>(x, wp, bp, out);
}